// round 15
// baseline (speedup 1.0000x reference)
#include <cuda_runtime.h>

#define Tt 2048
#define Dd 1024
#define Ff 4096
#define Ee 8
#define NROWS (Tt * 2)

typedef unsigned int u32;

// ---------------- scratch (device globals: allocation-free, graph-safe) ----------------
__device__ u32   g_x_tf[(size_t)Tt * Dd];        // x pre-rounded to tf32 bits
__device__ u32   g_wgT[(size_t)Ee * Ff * Dd];    // wg^T: [E][F][D] tf32 bits (K-major)
__device__ u32   g_wuT[(size_t)Ee * Ff * Dd];    // wu^T: [E][F][D]
__device__ u32   g_wdT[(size_t)Ee * Dd * Ff];    // wd^T: [E][D][F]
__device__ float g_fuse[(size_t)NROWS * Ff];     // compacted, stored tf32-rounded
__device__ float g_down[(size_t)NROWS * Dd];     // indexed by rid = t*2+k
__device__ int   g_bucket[NROWS];
__device__ int   g_offs[Ee + 1];
__device__ float g_topw[NROWS];
__device__ int   g_topidx[NROWS];

// ---------------- helpers ----------------
__device__ __forceinline__ u32 f2tf(float f) {
    u32 u;
    asm("cvt.rna.tf32.f32 %0, %1;" : "=r"(u) : "f"(f));
    return u;
}
__device__ __forceinline__ void mma8(float* c, const u32* a, u32 b0, u32 b1) {
    asm volatile(
        "mma.sync.aligned.m16n8k8.row.col.f32.tf32.tf32.f32 "
        "{%0,%1,%2,%3}, {%4,%5,%6,%7}, {%8,%9}, {%0,%1,%2,%3};"
        : "+f"(c[0]), "+f"(c[1]), "+f"(c[2]), "+f"(c[3])
        : "r"(a[0]), "r"(a[1]), "r"(a[2]), "r"(a[3]), "r"(b0), "r"(b1));
}
// ldmatrix x4: reg j of lane i = Mat_j[row i/4][u32 i%4]; Mats: (r0-7,k0-3),(r8-15,k0-3),(r0-7,k4-7),(r8-15,k4-7)
__device__ __forceinline__ void ldsm4(u32* r, u32 addr) {
    asm volatile("ldmatrix.sync.aligned.m8n8.x4.shared.b16 {%0,%1,%2,%3}, [%4];"
                 : "=r"(r[0]), "=r"(r[1]), "=r"(r[2]), "=r"(r[3]) : "r"(addr));
}
__device__ __forceinline__ float silu(float g) { return g / (1.f + __expf(-g)); }

#define CPA(d, s)   asm volatile("cp.async.cg.shared.global [%0], [%1], 16;" :: "r"(d), "l"(s))
#define CPCOMMIT()  asm volatile("cp.async.commit_group;" ::: "memory")
#define CPWAIT(n)   asm volatile("cp.async.wait_group %0;" :: "n"(n) : "memory")

// smem geometry (u32 units). All tiles [row][k32] stride 36 -> ldmatrix conflict-free (bank = lane).
#define AS 36
#define A_TILE_U32  (128 * AS)    // 4608
#define B1_TILE_U32 (64 * AS)     // 2304  (gemm1: 64-row B tiles)
#define B2_TILE_U32 (256 * AS)    // 9216  (gemm2: 256-row B tile)

// ---------------------- 1. Router ----------------------
__global__ void router_kernel(const float* __restrict__ x, const float* __restrict__ rw) {
    int gw   = (blockIdx.x * blockDim.x + threadIdx.x) >> 5;
    int lane = threadIdx.x & 31;
    if (gw >= Tt) return;
    const float* xr = x + (size_t)gw * Dd;
    float acc[Ee];
#pragma unroll
    for (int e = 0; e < Ee; e++) acc[e] = 0.f;
    for (int d = lane; d < Dd; d += 32) {
        float xv = xr[d];
        const float4* r = (const float4*)(rw + (size_t)d * Ee);
        float4 r0 = r[0], r1 = r[1];
        acc[0] += xv * r0.x; acc[1] += xv * r0.y;
        acc[2] += xv * r0.z; acc[3] += xv * r0.w;
        acc[4] += xv * r1.x; acc[5] += xv * r1.y;
        acc[6] += xv * r1.z; acc[7] += xv * r1.w;
    }
#pragma unroll
    for (int e = 0; e < Ee; e++) {
#pragma unroll
        for (int off = 16; off > 0; off >>= 1)
            acc[e] += __shfl_xor_sync(0xffffffffu, acc[e], off);
    }
    if (lane == 0) {
        int i0 = 0;
#pragma unroll
        for (int e = 1; e < Ee; e++) if (acc[e] > acc[i0]) i0 = e;
        int i1 = (i0 == 0) ? 1 : 0;
#pragma unroll
        for (int e = 0; e < Ee; e++) if (e != i0 && acc[e] > acc[i1]) i1 = e;
        float ex = __expf(acc[i1] - acc[i0]);
        float w0 = 1.f / (1.f + ex);
        g_topidx[gw * 2 + 0] = i0;
        g_topidx[gw * 2 + 1] = i1;
        g_topw[gw * 2 + 0] = w0;
        g_topw[gw * 2 + 1] = ex * w0;
    }
}

// ---------------------- 2. Bucket compaction ----------------------
__global__ void compact_kernel() {
    __shared__ int s_cnt[Ee], s_cur[Ee], s_off[Ee + 1];
    int tid = threadIdx.x;
    if (tid < Ee) { s_cnt[tid] = 0; s_cur[tid] = 0; }
    __syncthreads();
    for (int r = tid; r < NROWS; r += blockDim.x)
        atomicAdd(&s_cnt[g_topidx[r]], 1);
    __syncthreads();
    if (tid == 0) {
        int acc = 0;
        for (int e = 0; e < Ee; e++) { s_off[e] = acc; acc += s_cnt[e]; }
        s_off[Ee] = acc;
        for (int e = 0; e <= Ee; e++) g_offs[e] = s_off[e];
    }
    __syncthreads();
    for (int r = tid; r < NROWS; r += blockDim.x) {
        int e = g_topidx[r];
        int p = atomicAdd(&s_cur[e], 1);
        g_bucket[s_off[e] + p] = r;
    }
}

// ---------------------- 3a. x -> tf32 bits ----------------------
__global__ void convert_x_kernel(const float* __restrict__ x) {
    int i = blockIdx.x * blockDim.x + threadIdx.x;
    if (i >= Tt * Dd / 4) return;
    float4 v = ((const float4*)x)[i];
    ((uint4*)g_x_tf)[i] = make_uint4(f2tf(v.x), f2tf(v.y), f2tf(v.z), f2tf(v.w));
}

// ---------------------- 3b. weight transpose to K-major tf32 ----------------------
// in: W [E][R][C] fp32 (C contiguous). out: [E][C][R] u32 tf32 (R contiguous).
__global__ void transpose_tf_kernel(const float* __restrict__ w, int which, int R, int C) {
    u32* o = (which == 0) ? g_wgT : (which == 1) ? g_wuT : g_wdT;
    __shared__ float tile[32][33];
    const int e  = blockIdx.z;
    const int c0 = blockIdx.x * 32, r0 = blockIdx.y * 32;
    const int tx = threadIdx.x, ty = threadIdx.y;    // (32, 8)
    const size_t ib = (size_t)e * R * C;
#pragma unroll
    for (int i = 0; i < 32; i += 8)
        tile[ty + i][tx] = w[ib + (size_t)(r0 + ty + i) * C + (c0 + tx)];
    __syncthreads();
#pragma unroll
    for (int i = 0; i < 32; i += 8)
        o[ib + (size_t)(c0 + ty + i) * R + (r0 + tx)] = f2tf(tile[tx][ty + i]);
}

// ---------------------- 4. GEMM1: 256 thr, 2 CTAs/SM, all-ldmatrix, cp.async 3-stage ----------------------
// block 128M x 64N(gate)+64N(up), K-stage 32, warps 4Mx2N, warp tile 32x32
#define G1_STAGE_U32 (A_TILE_U32 + 2 * B1_TILE_U32)        // 9216
#define G1_STAGES 3
#define G1_SMEM_BYTES (G1_STAGES * G1_STAGE_U32 * 4)       // 110592

__global__ void __launch_bounds__(256, 2) gemm1_mma() {
    extern __shared__ u32 sm[];
    const int e   = blockIdx.z;
    const int off = g_offs[e];
    const int n_e = g_offs[e + 1] - off;
    const int m0  = blockIdx.x * 128;        // m fastest: weight-tile L2 reuse
    if (m0 >= n_e) return;
    const int n0  = blockIdx.y * 64;

    const u32 smb = (u32)__cvta_generic_to_shared(sm);
    const int tid = threadIdx.x, wid = tid >> 5, lane = tid & 31;
    const int g = lane >> 2, tig = lane & 3;
    const int wm = wid >> 1, wn = wid & 1;

    // ldmatrix per-lane source offset (u32 units) within a [row][k32]-stride-36 tile
    const int lmat = lane >> 3, lrow = lane & 7;
    const int aoff = ((lmat & 1) * 8 + lrow) * AS + (lmat >> 1) * 4;

    // cp.async loaders (256 thr): A 128 rows, 2 thr/row 64B; Bg/Bu 64 rows, 4 thr/row 32B
    const int arow = tid >> 1, aq = tid & 1;
    const int rid  = g_bucket[off + min(m0 + arow, n_e - 1)] >> 1;
    const char* aSrc = (const char*)(g_x_tf + (size_t)rid * Dd) + aq * 64;
    const int brow = tid >> 2, bq = tid & 3;
    const char* gSrc = (const char*)(g_wgT + (size_t)e * Ff * Dd + (size_t)(n0 + brow) * Dd) + bq * 32;
    const char* uSrc = (const char*)(g_wuT + (size_t)e * Ff * Dd + (size_t)(n0 + brow) * Dd) + bq * 32;
    const u32 aDst = smb + arow * (AS * 4) + aq * 64;
    const u32 gDst = smb + A_TILE_U32 * 4 + brow * (AS * 4) + bq * 32;
    const u32 uDst = smb + (A_TILE_U32 + B1_TILE_U32) * 4 + brow * (AS * 4) + bq * 32;

    auto issue = [&](int it, int s) {
        const u32 so = s * (G1_STAGE_U32 * 4);
        const size_t ko = (size_t)it * 128;               // 32 u32 along K
        CPA(aDst + so,      aSrc + ko);      CPA(aDst + so + 16, aSrc + ko + 16);
        CPA(aDst + so + 32, aSrc + ko + 32); CPA(aDst + so + 48, aSrc + ko + 48);
        CPA(gDst + so,      gSrc + ko);      CPA(gDst + so + 16, gSrc + ko + 16);
        CPA(uDst + so,      uSrc + ko);      CPA(uDst + so + 16, uSrc + ko + 16);
    };

    float cg[2][4][4], cu[2][4][4];
#pragma unroll
    for (int i = 0; i < 2; i++)
#pragma unroll
        for (int j = 0; j < 4; j++)
#pragma unroll
            for (int r = 0; r < 4; r++) { cg[i][j][r] = 0.f; cu[i][j][r] = 0.f; }

    const int NIT = Dd / 32;   // 32
    issue(0, 0); CPCOMMIT();
    issue(1, 1); CPCOMMIT();

#pragma unroll 1
    for (int it = 0; it < NIT; ++it) {
        const int s = it % 3;
        CPWAIT(1);
        __syncthreads();
        if (it + 2 < NIT) issue(it + 2, (it + 2) % 3);
        CPCOMMIT();

        const u32 stage = smb + s * (G1_STAGE_U32 * 4);
        const u32 Ab  = stage + (wm * 32 * AS + aoff) * 4;
        const u32 Bgb = stage + A_TILE_U32 * 4 + (wn * 32 * AS + aoff) * 4;
        const u32 Bub = stage + (A_TILE_U32 + B1_TILE_U32) * 4 + (wn * 32 * AS + aoff) * 4;

#pragma unroll
        for (int ks = 0; ks < 4; ++ks) {
            const int kk = ks * 8;
            u32 a[2][4], bg[2][4], bu[2][4];
            ldsm4(a[0],  Ab  + kk * 4);
            ldsm4(a[1],  Ab  + (16 * AS + kk) * 4);
            ldsm4(bg[0], Bgb + kk * 4);
            ldsm4(bg[1], Bgb + (16 * AS + kk) * 4);
            ldsm4(bu[0], Bub + kk * 4);
            ldsm4(bu[1], Bub + (16 * AS + kk) * 4);
#pragma unroll
            for (int nt = 0; nt < 4; nt++) {
                u32 bg0 = bg[nt >> 1][nt & 1], bg1 = bg[nt >> 1][(nt & 1) + 2];
                u32 bu0 = bu[nt >> 1][nt & 1], bu1 = bu[nt >> 1][(nt & 1) + 2];
#pragma unroll
                for (int mt = 0; mt < 2; mt++) {
                    mma8(cg[mt][nt], a[mt], bg0, bg1);
                    mma8(cu[mt][nt], a[mt], bu0, bu1);
                }
            }
        }
    }

    // epilogue: fuse = silu(gate)*up, stored tf32-rounded (consumed as tf32 by GEMM2)
#pragma unroll
    for (int mt = 0; mt < 2; mt++) {
#pragma unroll
        for (int nt = 0; nt < 4; nt++) {
            const int r0 = wm * 32 + mt * 16 + g;
            const int n  = n0 + wn * 32 + nt * 8 + 2 * tig;
            if (m0 + r0 < n_e) {
                float2 v;
                v.x = __uint_as_float(f2tf(silu(cg[mt][nt][0]) * cu[mt][nt][0]));
                v.y = __uint_as_float(f2tf(silu(cg[mt][nt][1]) * cu[mt][nt][1]));
                *(float2*)&g_fuse[(size_t)(off + m0 + r0) * Ff + n] = v;
            }
            if (m0 + r0 + 8 < n_e) {
                float2 v;
                v.x = __uint_as_float(f2tf(silu(cg[mt][nt][2]) * cu[mt][nt][2]));
                v.y = __uint_as_float(f2tf(silu(cg[mt][nt][3]) * cu[mt][nt][3]));
                *(float2*)&g_fuse[(size_t)(off + m0 + r0 + 8) * Ff + n] = v;
            }
        }
    }
}

// ---------------------- 5. GEMM2: 128M x 256N, all-ldmatrix, cp.async 4-stage ----------------------
// warps 4Mx4N, warp tile 32x64 (nt=8)
#define G2_STAGE_U32 (A_TILE_U32 + B2_TILE_U32)            // 13824
#define G2_STAGES 4
#define G2_SMEM_BYTES (G2_STAGES * G2_STAGE_U32 * 4)       // 221184

__global__ void __launch_bounds__(512, 1) gemm2_mma() {
    extern __shared__ u32 sm[];
    const int e   = blockIdx.z;
    const int off = g_offs[e];
    const int n_e = g_offs[e + 1] - off;
    const int m0  = blockIdx.x * 128;
    if (m0 >= n_e) return;
    const int n0  = blockIdx.y * 256;

    const u32 smb = (u32)__cvta_generic_to_shared(sm);
    const int tid = threadIdx.x, wid = tid >> 5, lane = tid & 31;
    const int g = lane >> 2, tig = lane & 3;
    const int wm = wid >> 2, wn = wid & 3;

    const int lmat = lane >> 3, lrow = lane & 7;
    const int aoff = ((lmat & 1) * 8 + lrow) * AS + (lmat >> 1) * 4;

    // loaders: A 128 rows, 4 thr/row 32B; B 256 rows, 2 thr/row 64B
    const int arow = tid >> 2, aq = tid & 3;
    const int ar   = off + min(m0 + arow, n_e - 1);
    const char* aSrc = (const char*)(g_fuse + (size_t)ar * Ff) + aq * 32;
    const int brow = tid >> 1, bq = tid & 1;
    const char* bSrc = (const char*)(g_wdT + (size_t)e * Dd * Ff + (size_t)(n0 + brow) * Ff) + bq * 64;
    const u32 aDst = smb + arow * (AS * 4) + aq * 32;
    const u32 bDst = smb + A_TILE_U32 * 4 + brow * (AS * 4) + bq * 64;

    auto issue = [&](int it, int s) {
        const u32 so = s * (G2_STAGE_U32 * 4);
        const size_t ko = (size_t)it * 128;
        CPA(aDst + so,      aSrc + ko);      CPA(aDst + so + 16, aSrc + ko + 16);
        CPA(bDst + so,      bSrc + ko);      CPA(bDst + so + 16, bSrc + ko + 16);
        CPA(bDst + so + 32, bSrc + ko + 32); CPA(bDst + so + 48, bSrc + ko + 48);
    };

    float c[2][8][4];
#pragma unroll
    for (int i = 0; i < 2; i++)
#pragma unroll
        for (int j = 0; j < 8; j++)
#pragma unroll
            for (int r = 0; r < 4; r++) c[i][j][r] = 0.f;

    const int NIT = Ff / 32;   // 128
    issue(0, 0); CPCOMMIT();
    issue(1, 1); CPCOMMIT();
    issue(2, 2); CPCOMMIT();

#pragma unroll 1
    for (int it = 0; it < NIT; ++it) {
        const int s = it & 3;
        CPWAIT(2);
        __syncthreads();
        if (it + 3 < NIT) issue(it + 3, (it + 3) & 3);
        CPCOMMIT();

        const u32 stage = smb + s * (G2_STAGE_U32 * 4);
        const u32 Ab = stage + (wm * 32 * AS + aoff) * 4;
        const u32 Bb = stage + A_TILE_U32 * 4 + (wn * 64 * AS + aoff) * 4;

#pragma unroll
        for (int ks = 0; ks < 4; ++ks) {
            const int kk = ks * 8;
            u32 a[2][4], bb[4][4];
            ldsm4(a[0], Ab + kk * 4);
            ldsm4(a[1], Ab + (16 * AS + kk) * 4);
#pragma unroll
            for (int q = 0; q < 4; q++)
                ldsm4(bb[q], Bb + (q * 16 * AS + kk) * 4);
#pragma unroll
            for (int nt = 0; nt < 8; nt++) {
                u32 b0 = bb[nt >> 1][nt & 1], b1 = bb[nt >> 1][(nt & 1) + 2];
#pragma unroll
                for (int mt = 0; mt < 2; mt++)
                    mma8(c[mt][nt], a[mt], b0, b1);
            }
        }
    }

    // epilogue: scatter rows by rid (each rid written exactly once)
#pragma unroll
    for (int mt = 0; mt < 2; mt++) {
        const int r0 = m0 + wm * 32 + mt * 16 + g;
        const int rlo = (r0 < n_e)     ? g_bucket[off + r0]     : -1;
        const int rhi = (r0 + 8 < n_e) ? g_bucket[off + r0 + 8] : -1;
#pragma unroll
        for (int nt = 0; nt < 8; nt++) {
            const int n = n0 + wn * 64 + nt * 8 + 2 * tig;
            if (rlo >= 0) {
                float2 v; v.x = c[mt][nt][0]; v.y = c[mt][nt][1];
                *(float2*)&g_down[(size_t)rlo * Dd + n] = v;
            }
            if (rhi >= 0) {
                float2 v; v.x = c[mt][nt][2]; v.y = c[mt][nt][3];
                *(float2*)&g_down[(size_t)rhi * Dd + n] = v;
            }
        }
    }
}

// ---------------------- 6. Weighted combine ----------------------
__global__ void combine_kernel(float* __restrict__ out) {
    int i = blockIdx.x * blockDim.x + threadIdx.x;
    const int n4 = Tt * Dd / 4;
    if (i >= n4) return;
    int t = i / (Dd / 4);
    int c = i % (Dd / 4);
    float w0 = g_topw[t * 2 + 0];
    float w1 = g_topw[t * 2 + 1];
    float4 a = ((const float4*)(g_down + (size_t)(t * 2 + 0) * Dd))[c];
    float4 b = ((const float4*)(g_down + (size_t)(t * 2 + 1) * Dd))[c];
    float4 r;
    r.x = w0 * a.x + w1 * b.x;
    r.y = w0 * a.y + w1 * b.y;
    r.z = w0 * a.z + w1 * b.z;
    r.w = w0 * a.w + w1 * b.w;
    ((float4*)out)[i] = r;
}

// ---------------------- launch ----------------------
extern "C" void kernel_launch(void* const* d_in, const int* in_sizes, int n_in,
                              void* d_out, int out_size) {
    const float* x  = (const float*)d_in[0];
    const float* rw = (const float*)d_in[1];
    const float* wg = (const float*)d_in[2];
    const float* wu = (const float*)d_in[3];
    const float* wd = (const float*)d_in[4];
    float* out = (float*)d_out;

    static int configured = 0;
    if (!configured) {
        cudaFuncSetAttribute(gemm1_mma, cudaFuncAttributeMaxDynamicSharedMemorySize, G1_SMEM_BYTES);
        cudaFuncSetAttribute(gemm2_mma, cudaFuncAttributeMaxDynamicSharedMemorySize, G2_SMEM_BYTES);
        configured = 1;
    }

    router_kernel<<<Tt / 8, 256>>>(x, rw);
    compact_kernel<<<1, 256>>>();
    convert_x_kernel<<<(Tt * Dd / 4 + 255) / 256, 256>>>(x);

    dim3 tb(32, 8);
    transpose_tf_kernel<<<dim3(Ff / 32, Dd / 32, Ee), tb>>>(wg, 0, Dd, Ff);
    transpose_tf_kernel<<<dim3(Ff / 32, Dd / 32, Ee), tb>>>(wu, 1, Dd, Ff);
    transpose_tf_kernel<<<dim3(Dd / 32, Ff / 32, Ee), tb>>>(wd, 2, Ff, Dd);

    dim3 g1(NROWS / 128, Ff / 64, Ee);   // m fastest: weight-tile L2 reuse
    gemm1_mma<<<g1, 256, G1_SMEM_BYTES>>>();

    dim3 g2(NROWS / 128, Dd / 256, Ee);
    gemm2_mma<<<g2, 512, G2_SMEM_BYTES>>>();

    combine_kernel<<<(Tt * Dd / 4 + 255) / 256, 256>>>(out);
}

// round 16
// speedup vs baseline: 1.2112x; 1.2112x over previous
#include <cuda_runtime.h>

#define Tt 2048
#define Dd 1024
#define Ff 4096
#define Ee 8
#define NROWS (Tt * 2)

typedef unsigned int u32;

// ---------------- scratch (device globals: allocation-free, graph-safe) ----------------
__device__ u32   g_x_tf[(size_t)Tt * Dd];        // x pre-rounded to tf32 bits
__device__ u32   g_wdT[(size_t)Ee * Dd * Ff];    // wd^T: [E][D][F] tf32 bits (K-major)
__device__ float g_fuse[(size_t)NROWS * Ff];     // compacted, stored tf32-rounded
__device__ float g_down[(size_t)NROWS * Dd];     // indexed by rid = t*2+k
__device__ int   g_bucket[NROWS];
__device__ int   g_offs[Ee + 1];
__device__ float g_topw[NROWS];
__device__ int   g_topidx[NROWS];

// ---------------- helpers ----------------
__device__ __forceinline__ u32 f2tf(float f) {
    u32 u;
    asm("cvt.rna.tf32.f32 %0, %1;" : "=r"(u) : "f"(f));
    return u;
}
__device__ __forceinline__ void mma8(float* c, const u32* a, u32 b0, u32 b1) {
    asm volatile(
        "mma.sync.aligned.m16n8k8.row.col.f32.tf32.tf32.f32 "
        "{%0,%1,%2,%3}, {%4,%5,%6,%7}, {%8,%9}, {%0,%1,%2,%3};"
        : "+f"(c[0]), "+f"(c[1]), "+f"(c[2]), "+f"(c[3])
        : "r"(a[0]), "r"(a[1]), "r"(a[2]), "r"(a[3]), "r"(b0), "r"(b1));
}
// ldmatrix x4: reg j of lane i = Mat_j[row i/4][u32 i%4]; Mats: (r0-7,k0-3),(r8-15,k0-3),(r0-7,k4-7),(r8-15,k4-7)
__device__ __forceinline__ void ldsm4(u32* r, u32 addr) {
    asm volatile("ldmatrix.sync.aligned.m8n8.x4.shared.b16 {%0,%1,%2,%3}, [%4];"
                 : "=r"(r[0]), "=r"(r[1]), "=r"(r[2]), "=r"(r[3]) : "r"(addr));
}
__device__ __forceinline__ float silu(float g) { return g / (1.f + __expf(-g)); }

#define CPA(d, s)   asm volatile("cp.async.cg.shared.global [%0], [%1], 16;" :: "r"(d), "l"(s))
#define CPCOMMIT()  asm volatile("cp.async.commit_group;" ::: "memory")
#define CPWAIT(n)   asm volatile("cp.async.wait_group %0;" :: "n"(n) : "memory")

// smem geometry (u32 units).
// A / wd^T tiles: [row][k32] stride 36 -> ldmatrix conflict-free (bank = lane)
// gemm1 B tiles:  [k32][128 n] stride 136 -> LDS bank = (8*tig + g) permutation, conflict-free
#define AS 36
#define BS 136
#define A_TILE_U32  (128 * AS)    // 4608
#define B_TILE_U32  (32 * BS)     // 4352
#define B2_TILE_U32 (256 * AS)    // 9216

// ---------------------- 1. Router ----------------------
__global__ void router_kernel(const float* __restrict__ x, const float* __restrict__ rw) {
    int gw   = (blockIdx.x * blockDim.x + threadIdx.x) >> 5;
    int lane = threadIdx.x & 31;
    if (gw >= Tt) return;
    const float* xr = x + (size_t)gw * Dd;
    float acc[Ee];
#pragma unroll
    for (int e = 0; e < Ee; e++) acc[e] = 0.f;
    for (int d = lane; d < Dd; d += 32) {
        float xv = xr[d];
        const float4* r = (const float4*)(rw + (size_t)d * Ee);
        float4 r0 = r[0], r1 = r[1];
        acc[0] += xv * r0.x; acc[1] += xv * r0.y;
        acc[2] += xv * r0.z; acc[3] += xv * r0.w;
        acc[4] += xv * r1.x; acc[5] += xv * r1.y;
        acc[6] += xv * r1.z; acc[7] += xv * r1.w;
    }
#pragma unroll
    for (int e = 0; e < Ee; e++) {
#pragma unroll
        for (int off = 16; off > 0; off >>= 1)
            acc[e] += __shfl_xor_sync(0xffffffffu, acc[e], off);
    }
    if (lane == 0) {
        int i0 = 0;
#pragma unroll
        for (int e = 1; e < Ee; e++) if (acc[e] > acc[i0]) i0 = e;
        int i1 = (i0 == 0) ? 1 : 0;
#pragma unroll
        for (int e = 0; e < Ee; e++) if (e != i0 && acc[e] > acc[i1]) i1 = e;
        float ex = __expf(acc[i1] - acc[i0]);
        float w0 = 1.f / (1.f + ex);
        g_topidx[gw * 2 + 0] = i0;
        g_topidx[gw * 2 + 1] = i1;
        g_topw[gw * 2 + 0] = w0;
        g_topw[gw * 2 + 1] = ex * w0;
    }
}

// ---------------------- 2. Bucket compaction ----------------------
__global__ void compact_kernel() {
    __shared__ int s_cnt[Ee], s_cur[Ee], s_off[Ee + 1];
    int tid = threadIdx.x;
    if (tid < Ee) { s_cnt[tid] = 0; s_cur[tid] = 0; }
    __syncthreads();
    for (int r = tid; r < NROWS; r += blockDim.x)
        atomicAdd(&s_cnt[g_topidx[r]], 1);
    __syncthreads();
    if (tid == 0) {
        int acc = 0;
        for (int e = 0; e < Ee; e++) { s_off[e] = acc; acc += s_cnt[e]; }
        s_off[Ee] = acc;
        for (int e = 0; e <= Ee; e++) g_offs[e] = s_off[e];
    }
    __syncthreads();
    for (int r = tid; r < NROWS; r += blockDim.x) {
        int e = g_topidx[r];
        int p = atomicAdd(&s_cur[e], 1);
        g_bucket[s_off[e] + p] = r;
    }
}

// ---------------------- 3a. x -> tf32 bits ----------------------
__global__ void convert_x_kernel(const float* __restrict__ x) {
    int i = blockIdx.x * blockDim.x + threadIdx.x;
    if (i >= Tt * Dd / 4) return;
    float4 v = ((const float4*)x)[i];
    ((uint4*)g_x_tf)[i] = make_uint4(f2tf(v.x), f2tf(v.y), f2tf(v.z), f2tf(v.w));
}

// ---------------------- 3b. wd transpose to K-major tf32 ----------------------
// in: wd [E][F][D] fp32 (D contiguous). out: [E][D][F] u32 tf32 (F contiguous).
__global__ void transpose_tf_kernel(const float* __restrict__ w, int R, int C) {
    __shared__ float tile[32][33];
    const int e  = blockIdx.z;
    const int c0 = blockIdx.x * 32, r0 = blockIdx.y * 32;
    const int tx = threadIdx.x, ty = threadIdx.y;    // (32, 8)
    const size_t ib = (size_t)e * R * C;
#pragma unroll
    for (int i = 0; i < 32; i += 8)
        tile[ty + i][tx] = w[ib + (size_t)(r0 + ty + i) * C + (c0 + tx)];
    __syncthreads();
#pragma unroll
    for (int i = 0; i < 32; i += 8)
        g_wdT[ib + (size_t)(c0 + ty + i) * R + (r0 + tx)] = f2tf(tile[tx][ty + i]);
}

// ---------------------- 4. GEMM1: 512 thr, cp.async 4-stage, warp grid 2Mx8N ----------------------
// block 128M x 128N(gate)+128N(up), K-stage 32, warp tile 64x16
// issue balance: A-ldsm 16/stage, B-LDS+cvt 64/stage (was 8 / 128 with 4Mx4N)
#define G1_STAGE_U32 (A_TILE_U32 + 2 * B_TILE_U32)         // 13312
#define G1_STAGES 4
#define G1_SMEM_BYTES (G1_STAGES * G1_STAGE_U32 * 4)       // 212992

__global__ void __launch_bounds__(512, 1) gemm1_mma(
    const float* __restrict__ wg, const float* __restrict__ wu)
{
    extern __shared__ u32 sm[];
    const int e   = blockIdx.z;
    const int off = g_offs[e];
    const int n_e = g_offs[e + 1] - off;
    const int m0  = blockIdx.x * 128;        // m fastest: weight-tile L2 reuse
    if (m0 >= n_e) return;
    const int n0  = blockIdx.y * 128;

    const u32 smb = (u32)__cvta_generic_to_shared(sm);
    const int tid = threadIdx.x, wid = tid >> 5, lane = tid & 31;
    const int g = lane >> 2, tig = lane & 3;
    const int wm = wid >> 3, wn = wid & 7;   // 2M x 8N

    // ldmatrix per-lane source offset (u32 units) within [row][k32]-stride-36 A tile
    const int lmat = lane >> 3, lrow = lane & 7;
    const int aoff = ((lmat & 1) * 8 + lrow) * AS + (lmat >> 1) * 4;

    // cp.async loaders: A: 4 thr/row, 32B each; B: 16 thr/k-row, 32B each
    const int arow = tid >> 2, aq = tid & 3;
    const int rid  = g_bucket[off + min(m0 + arow, n_e - 1)] >> 1;
    const char* aSrc = (const char*)(g_x_tf + (size_t)rid * Dd) + aq * 32;
    const int kb = tid >> 4, oct = tid & 15;
    const char* gSrc = (const char*)(wg + (size_t)e * Dd * Ff + (size_t)kb * Ff + n0) + oct * 32;
    const char* uSrc = (const char*)(wu + (size_t)e * Dd * Ff + (size_t)kb * Ff + n0) + oct * 32;
    const u32 aDst = smb + arow * (AS * 4) + aq * 32;
    const u32 gDst = smb + A_TILE_U32 * 4 + kb * (BS * 4) + oct * 32;
    const u32 uDst = gDst + B_TILE_U32 * 4;

    auto issue = [&](int it, int s) {
        const u32 so = s * (G1_STAGE_U32 * 4);
        const size_t ko = (size_t)it * 128;                // 32 u32 along K
        const char* gs = gSrc + (size_t)it * (32 * Ff * 4);
        const char* us = uSrc + (size_t)it * (32 * Ff * 4);
        CPA(aDst + so,      aSrc + ko);   CPA(aDst + so + 16, aSrc + ko + 16);
        CPA(gDst + so,      gs);          CPA(gDst + so + 16, gs + 16);
        CPA(uDst + so,      us);          CPA(uDst + so + 16, us + 16);
    };

    float cg[4][2][4], cu[4][2][4];
#pragma unroll
    for (int i = 0; i < 4; i++)
#pragma unroll
        for (int j = 0; j < 2; j++)
#pragma unroll
            for (int r = 0; r < 4; r++) { cg[i][j][r] = 0.f; cu[i][j][r] = 0.f; }

    const int NIT = Dd / 32;   // 32
    issue(0, 0); CPCOMMIT();
    issue(1, 1); CPCOMMIT();
    issue(2, 2); CPCOMMIT();

#pragma unroll 1
    for (int it = 0; it < NIT; ++it) {
        const int s = it & 3;
        CPWAIT(2);
        __syncthreads();
        if (it + 3 < NIT) issue(it + 3, (it + 3) & 3);
        CPCOMMIT();

        const u32 Ab = smb + s * (G1_STAGE_U32 * 4) + (wm * 64 * AS + aoff) * 4;
        const u32* Bg = sm + s * G1_STAGE_U32 + A_TILE_U32;
        const u32* Bu = Bg + B_TILE_U32;

#pragma unroll
        for (int ks = 0; ks < 4; ++ks) {
            const int kk = ks * 8;
            u32 a[4][4];
#pragma unroll
            for (int mt = 0; mt < 4; mt++)
                ldsm4(a[mt], Ab + (mt * 16 * AS + kk) * 4);
#pragma unroll
            for (int nt = 0; nt < 2; nt++) {
                const int nb = wn * 16 + nt * 8 + g;
                u32 bg0 = f2tf(__uint_as_float(Bg[(kk + tig) * BS + nb]));
                u32 bg1 = f2tf(__uint_as_float(Bg[(kk + tig + 4) * BS + nb]));
                u32 bu0 = f2tf(__uint_as_float(Bu[(kk + tig) * BS + nb]));
                u32 bu1 = f2tf(__uint_as_float(Bu[(kk + tig + 4) * BS + nb]));
#pragma unroll
                for (int mt = 0; mt < 4; mt++) {
                    mma8(cg[mt][nt], a[mt], bg0, bg1);
                    mma8(cu[mt][nt], a[mt], bu0, bu1);
                }
            }
        }
    }

    // epilogue: fuse = silu(gate)*up, stored tf32-rounded (consumed as tf32 by GEMM2)
#pragma unroll
    for (int mt = 0; mt < 4; mt++) {
#pragma unroll
        for (int nt = 0; nt < 2; nt++) {
            const int r0 = wm * 64 + mt * 16 + g;
            const int n  = n0 + wn * 16 + nt * 8 + 2 * tig;
            if (m0 + r0 < n_e) {
                float2 v;
                v.x = __uint_as_float(f2tf(silu(cg[mt][nt][0]) * cu[mt][nt][0]));
                v.y = __uint_as_float(f2tf(silu(cg[mt][nt][1]) * cu[mt][nt][1]));
                *(float2*)&g_fuse[(size_t)(off + m0 + r0) * Ff + n] = v;
            }
            if (m0 + r0 + 8 < n_e) {
                float2 v;
                v.x = __uint_as_float(f2tf(silu(cg[mt][nt][2]) * cu[mt][nt][2]));
                v.y = __uint_as_float(f2tf(silu(cg[mt][nt][3]) * cu[mt][nt][3]));
                *(float2*)&g_fuse[(size_t)(off + m0 + r0 + 8) * Ff + n] = v;
            }
        }
    }
}

// ---------------------- 5. GEMM2: 128M x 256N, all-ldmatrix, cp.async 4-stage ----------------------
// warps 4Mx4N, warp tile 32x64 (nt=8)  [R14 version, tested]
#define G2_STAGE_U32 (A_TILE_U32 + B2_TILE_U32)            // 13824
#define G2_STAGES 4
#define G2_SMEM_BYTES (G2_STAGES * G2_STAGE_U32 * 4)       // 221184

__global__ void __launch_bounds__(512, 1) gemm2_mma() {
    extern __shared__ u32 sm[];
    const int e   = blockIdx.z;
    const int off = g_offs[e];
    const int n_e = g_offs[e + 1] - off;
    const int m0  = blockIdx.x * 128;
    if (m0 >= n_e) return;
    const int n0  = blockIdx.y * 256;

    const u32 smb = (u32)__cvta_generic_to_shared(sm);
    const int tid = threadIdx.x, wid = tid >> 5, lane = tid & 31;
    const int g = lane >> 2, tig = lane & 3;
    const int wm = wid >> 2, wn = wid & 3;

    const int lmat = lane >> 3, lrow = lane & 7;
    const int aoff = ((lmat & 1) * 8 + lrow) * AS + (lmat >> 1) * 4;

    // loaders: A 128 rows, 4 thr/row 32B; B 256 rows, 2 thr/row 64B
    const int arow = tid >> 2, aq = tid & 3;
    const int ar   = off + min(m0 + arow, n_e - 1);
    const char* aSrc = (const char*)(g_fuse + (size_t)ar * Ff) + aq * 32;
    const int brow = tid >> 1, bq = tid & 1;
    const char* bSrc = (const char*)(g_wdT + (size_t)e * Dd * Ff + (size_t)(n0 + brow) * Ff) + bq * 64;
    const u32 aDst = smb + arow * (AS * 4) + aq * 32;
    const u32 bDst = smb + A_TILE_U32 * 4 + brow * (AS * 4) + bq * 64;

    auto issue = [&](int it, int s) {
        const u32 so = s * (G2_STAGE_U32 * 4);
        const size_t ko = (size_t)it * 128;
        CPA(aDst + so,      aSrc + ko);      CPA(aDst + so + 16, aSrc + ko + 16);
        CPA(bDst + so,      bSrc + ko);      CPA(bDst + so + 16, bSrc + ko + 16);
        CPA(bDst + so + 32, bSrc + ko + 32); CPA(bDst + so + 48, bSrc + ko + 48);
    };

    float c[2][8][4];
#pragma unroll
    for (int i = 0; i < 2; i++)
#pragma unroll
        for (int j = 0; j < 8; j++)
#pragma unroll
            for (int r = 0; r < 4; r++) c[i][j][r] = 0.f;

    const int NIT = Ff / 32;   // 128
    issue(0, 0); CPCOMMIT();
    issue(1, 1); CPCOMMIT();
    issue(2, 2); CPCOMMIT();

#pragma unroll 1
    for (int it = 0; it < NIT; ++it) {
        const int s = it & 3;
        CPWAIT(2);
        __syncthreads();
        if (it + 3 < NIT) issue(it + 3, (it + 3) & 3);
        CPCOMMIT();

        const u32 stage = smb + s * (G2_STAGE_U32 * 4);
        const u32 Ab = stage + (wm * 32 * AS + aoff) * 4;
        const u32 Bb = stage + A_TILE_U32 * 4 + (wn * 64 * AS + aoff) * 4;

#pragma unroll
        for (int ks = 0; ks < 4; ++ks) {
            const int kk = ks * 8;
            u32 a[2][4], bb[4][4];
            ldsm4(a[0], Ab + kk * 4);
            ldsm4(a[1], Ab + (16 * AS + kk) * 4);
#pragma unroll
            for (int q = 0; q < 4; q++)
                ldsm4(bb[q], Bb + (q * 16 * AS + kk) * 4);
#pragma unroll
            for (int nt = 0; nt < 8; nt++) {
                u32 b0 = bb[nt >> 1][nt & 1], b1 = bb[nt >> 1][(nt & 1) + 2];
#pragma unroll
                for (int mt = 0; mt < 2; mt++)
                    mma8(c[mt][nt], a[mt], b0, b1);
            }
        }
    }

    // epilogue: scatter rows by rid (each rid written exactly once)
#pragma unroll
    for (int mt = 0; mt < 2; mt++) {
        const int r0 = m0 + wm * 32 + mt * 16 + g;
        const int rlo = (r0 < n_e)     ? g_bucket[off + r0]     : -1;
        const int rhi = (r0 + 8 < n_e) ? g_bucket[off + r0 + 8] : -1;
#pragma unroll
        for (int nt = 0; nt < 8; nt++) {
            const int n = n0 + wn * 64 + nt * 8 + 2 * tig;
            if (rlo >= 0) {
                float2 v; v.x = c[mt][nt][0]; v.y = c[mt][nt][1];
                *(float2*)&g_down[(size_t)rlo * Dd + n] = v;
            }
            if (rhi >= 0) {
                float2 v; v.x = c[mt][nt][2]; v.y = c[mt][nt][3];
                *(float2*)&g_down[(size_t)rhi * Dd + n] = v;
            }
        }
    }
}

// ---------------------- 6. Weighted combine ----------------------
__global__ void combine_kernel(float* __restrict__ out) {
    int i = blockIdx.x * blockDim.x + threadIdx.x;
    const int n4 = Tt * Dd / 4;
    if (i >= n4) return;
    int t = i / (Dd / 4);
    int c = i % (Dd / 4);
    float w0 = g_topw[t * 2 + 0];
    float w1 = g_topw[t * 2 + 1];
    float4 a = ((const float4*)(g_down + (size_t)(t * 2 + 0) * Dd))[c];
    float4 b = ((const float4*)(g_down + (size_t)(t * 2 + 1) * Dd))[c];
    float4 r;
    r.x = w0 * a.x + w1 * b.x;
    r.y = w0 * a.y + w1 * b.y;
    r.z = w0 * a.z + w1 * b.z;
    r.w = w0 * a.w + w1 * b.w;
    ((float4*)out)[i] = r;
}

// ---------------------- launch ----------------------
extern "C" void kernel_launch(void* const* d_in, const int* in_sizes, int n_in,
                              void* d_out, int out_size) {
    const float* x  = (const float*)d_in[0];
    const float* rw = (const float*)d_in[1];
    const float* wg = (const float*)d_in[2];
    const float* wu = (const float*)d_in[3];
    const float* wd = (const float*)d_in[4];
    float* out = (float*)d_out;

    static int configured = 0;
    if (!configured) {
        cudaFuncSetAttribute(gemm1_mma, cudaFuncAttributeMaxDynamicSharedMemorySize, G1_SMEM_BYTES);
        cudaFuncSetAttribute(gemm2_mma, cudaFuncAttributeMaxDynamicSharedMemorySize, G2_SMEM_BYTES);
        configured = 1;
    }

    router_kernel<<<Tt / 8, 256>>>(x, rw);
    compact_kernel<<<1, 256>>>();
    convert_x_kernel<<<(Tt * Dd / 4 + 255) / 256, 256>>>(x);

    dim3 tb(32, 8);
    transpose_tf_kernel<<<dim3(Dd / 32, Ff / 32, Ee), tb>>>(wd, Ff, Dd);   // wd only

    dim3 g1(NROWS / 128, Ff / 128, Ee);   // m fastest: weight-tile L2 reuse
    gemm1_mma<<<g1, 512, G1_SMEM_BYTES>>>(wg, wu);

    dim3 g2(NROWS / 128, Dd / 256, Ee);
    gemm2_mma<<<g2, 512, G2_SMEM_BYTES>>>();

    combine_kernel<<<(Tt * Dd / 4 + 255) / 256, 256>>>(out);
}